// round 3
// baseline (speedup 1.0000x reference)
#include <cuda_runtime.h>
#include <cuda_bf16.h>
#include <cstdint>

#define N_NODES 50000
#define N_EDGES 800000
#define D 96

// -------- scratch (static device globals; no allocation allowed) --------
__device__ __align__(16) float g_xw [N_NODES * D];   // X @ W (current layer)
__device__ __align__(16) float g_h  [N_NODES * D];   // layer-1 output
__device__ float g_dinv[N_NODES];                    // 1/sqrt(deg)
__device__ int   g_cnt [N_NODES];                    // in-degree histogram
__device__ int   g_cur [N_NODES];                    // fill cursors
__device__ int   g_rowptr[N_NODES + 1];              // CSR row pointers (by dst)
__device__ int   g_csr [N_EDGES];                    // CSR column indices (src)

// ---------------- CSR build ----------------
__global__ void k_zero() {
    int i = blockIdx.x * blockDim.x + threadIdx.x;
    if (i < N_NODES) { g_cnt[i] = 0; g_cur[i] = 0; }
}

__global__ void k_count(const int* __restrict__ dst) {
    int e = blockIdx.x * blockDim.x + threadIdx.x;
    if (e < N_EDGES) atomicAdd(&g_cnt[dst[e]], 1);
}

// single-CTA exclusive prefix scan over 50k bins; also writes dinv
__global__ void __launch_bounds__(1024) k_scan() {
    __shared__ int ssum[1024];
    const int T = 1024;
    const int CHUNK = (N_NODES + T - 1) / T;   // 49
    int t = threadIdx.x;
    int beg = t * CHUNK;
    int end = min(beg + CHUNK, N_NODES);
    int local = 0;
    for (int i = beg; i < end; i++) local += g_cnt[i];
    ssum[t] = local;
    __syncthreads();
    if (t == 0) {
        int acc = 0;
        for (int i = 0; i < T; i++) { int v = ssum[i]; ssum[i] = acc; acc += v; }
        g_rowptr[N_NODES] = acc;   // == N_EDGES
    }
    __syncthreads();
    int acc = ssum[t];
    for (int i = beg; i < end; i++) {
        g_rowptr[i] = acc;
        int c = g_cnt[i];
        acc += c;
        g_dinv[i] = rsqrtf(1.0f + (float)c);   // self-loop included
    }
}

__global__ void k_fill(const int* __restrict__ src,
                       const int* __restrict__ dst) {
    int e = blockIdx.x * blockDim.x + threadIdx.x;
    if (e >= N_EDGES) return;
    int d = dst[e];
    int pos = g_rowptr[d] + atomicAdd(&g_cur[d], 1);
    g_csr[pos] = src[e];
}

// ---------------- GEMM: g_xw[N,96] = X[N,96] @ W[96,96] ----------------
// 256 threads / block, 32 rows / block. Thread (ty=t>>5, tx=t&31) computes
// rows ty*4..+3, cols tx*3..+2. Ws reads stride-3 across lanes (conflict-
// free since gcd(3,32)=1); Xs reads broadcast within a warp.
__global__ void __launch_bounds__(256)
k_gemm(const float* __restrict__ Xext, const float* __restrict__ W, int use_h) {
    __shared__ float Ws[D * D];        // 36864 B
    __shared__ float Xs[32 * D];       // 12288 B
    const float* __restrict__ X = use_h ? (const float*)g_h : Xext;

    int t = threadIdx.x;
    int rowBase = blockIdx.x * 32;

    for (int i = t; i < D * D; i += 256) Ws[i] = W[i];
    for (int i = t; i < 32 * D; i += 256) {
        int r = rowBase + i / D;
        Xs[i] = (r < N_NODES) ? X[r * D + (i % D)] : 0.0f;
    }
    __syncthreads();

    int ty = t >> 5, tx = t & 31;
    float acc[4][3] = {};
    #pragma unroll 4
    for (int k = 0; k < D; k++) {
        float w0 = Ws[k * D + tx * 3 + 0];
        float w1 = Ws[k * D + tx * 3 + 1];
        float w2 = Ws[k * D + tx * 3 + 2];
        #pragma unroll
        for (int r = 0; r < 4; r++) {
            float xv = Xs[(ty * 4 + r) * D + k];
            acc[r][0] += xv * w0;
            acc[r][1] += xv * w1;
            acc[r][2] += xv * w2;
        }
    }
    #pragma unroll
    for (int r = 0; r < 4; r++) {
        int row = rowBase + ty * 4 + r;
        if (row < N_NODES) {
            g_xw[row * D + tx * 3 + 0] = acc[r][0];
            g_xw[row * D + tx * 3 + 1] = acc[r][1];
            g_xw[row * D + tx * 3 + 2] = acc[r][2];
        }
    }
}

// ---------------- fused aggregate + bias + relu ----------------
// One warp per node; lane handles columns {lane, lane+32, lane+64}.
// out[i] = relu( dinv_i * ( dinv_i*xw_i + sum_s dinv_s*xw_s ) + b )
__global__ void __launch_bounds__(256)
k_agg(const float* __restrict__ b, float* __restrict__ outExt, int to_h) {
    int warp = (blockIdx.x * blockDim.x + threadIdx.x) >> 5;
    int lane = threadIdx.x & 31;
    if (warp >= N_NODES) return;
    int i = warp;

    float di = g_dinv[i];
    const float* __restrict__ xwi = g_xw + (size_t)i * D;
    float a0 = xwi[lane]      * di;
    float a1 = xwi[lane + 32] * di;
    float a2 = xwi[lane + 64] * di;

    int beg = g_rowptr[i];
    int end = g_rowptr[i + 1];
    for (int j = beg; j < end; j++) {
        int s = g_csr[j];                 // broadcast within warp
        float ws = g_dinv[s];             // broadcast within warp
        const float* __restrict__ xs = g_xw + (size_t)s * D;
        a0 += xs[lane]      * ws;         // 128B coalesced
        a1 += xs[lane + 32] * ws;
        a2 += xs[lane + 64] * ws;
    }

    float* __restrict__ out = to_h ? g_h : outExt;
    float* op = out + (size_t)i * D;
    op[lane]      = fmaxf(a0 * di + b[lane],      0.0f);
    op[lane + 32] = fmaxf(a1 * di + b[lane + 32], 0.0f);
    op[lane + 64] = fmaxf(a2 * di + b[lane + 64], 0.0f);
}

// ---------------- launch ----------------
extern "C" void kernel_launch(void* const* d_in, const int* in_sizes, int n_in,
                              void* d_out, int out_size) {
    const float* x   = (const float*)d_in[0];
    const int*   ei  = (const int*)d_in[1];   // [2, E] int32 (JAX x64 disabled)
    const float* W1  = (const float*)d_in[2];
    const float* b1  = (const float*)d_in[3];
    const float* W2  = (const float*)d_in[4];
    const float* b2  = (const float*)d_in[5];
    float*       out = (float*)d_out;

    const int* src = ei;
    const int* dst = ei + N_EDGES;

    const int T = 256;
    int gN    = (N_NODES + T - 1) / T;
    int gE    = (N_EDGES + T - 1) / T;
    int gGemm = (N_NODES + 31) / 32;
    int gAgg  = (N_NODES * 32 + T - 1) / T;   // warp per node

    // CSR build + norms (shared by both layers)
    k_zero  <<<gN, T>>>();
    k_count <<<gE, T>>>(dst);
    k_scan  <<<1, 1024>>>();
    k_fill  <<<gE, T>>>(src, dst);

    // layer 1: h = relu(agg(x @ W1) + b1)
    k_gemm <<<gGemm, T>>>(x, W1, 0);
    k_agg  <<<gAgg, T>>>(b1, out, 1);

    // layer 2: out = relu(agg(h @ W2) + b2)
    k_gemm <<<gGemm, T>>>(nullptr, W2, 1);
    k_agg  <<<gAgg, T>>>(b2, out, 0);
}

// round 4
// speedup vs baseline: 1.0745x; 1.0745x over previous
#include <cuda_runtime.h>
#include <cuda_bf16.h>
#include <cstdint>

#define N_NODES 50000
#define N_EDGES 800000
#define D 96
#define GR 64   // rows per GEMM block

// -------- scratch (static device globals; no allocation allowed) --------
__device__ __align__(16) float g_xw [N_NODES * D];   // X @ W (current layer)
__device__ __align__(16) float g_h  [N_NODES * D];   // layer-1 output
__device__ float g_dinv[N_NODES];                    // 1/sqrt(deg)
__device__ int   g_cnt [N_NODES];                    // in-degree histogram
__device__ int   g_cur [N_NODES];                    // fill cursors
__device__ int   g_rowptr[N_NODES + 1];              // CSR row pointers (by dst)
__device__ int   g_csr [N_EDGES];                    // CSR column indices (src)

#define FMA_F32X2(d, a, b, c) \
    asm("fma.rn.f32x2 %0, %1, %2, %3;" : "=l"(d) : "l"(a), "l"(b), "l"(c))
#define PACK_F32X2(out, lo, hi) \
    asm("mov.b64 %0, {%1, %2};" : "=l"(out) : "f"(lo), "f"(hi))
#define UNPACK_F32X2(lo, hi, in) \
    asm("mov.b64 {%0, %1}, %2;" : "=f"(lo), "=f"(hi) : "l"(in))

// ---------------- CSR build ----------------
__global__ void k_zero() {
    int i = blockIdx.x * blockDim.x + threadIdx.x;
    if (i < N_NODES) { g_cnt[i] = 0; g_cur[i] = 0; }
}

__global__ void k_count(const int* __restrict__ dst) {
    int e = blockIdx.x * blockDim.x + threadIdx.x;
    if (e < N_EDGES) atomicAdd(&g_cnt[dst[e]], 1);
}

// single-CTA exclusive prefix scan over 50k bins (hierarchical); writes dinv
__global__ void __launch_bounds__(1024) k_scan() {
    __shared__ int wsum[32];
    const int T = 1024;
    const int CHUNK = (N_NODES + T - 1) / T;   // 49
    int t = threadIdx.x;
    int lane = t & 31, wid = t >> 5;
    int beg = t * CHUNK;
    int end = min(beg + CHUNK, N_NODES);
    if (beg > N_NODES) beg = N_NODES;
    if (end < beg) end = beg;

    int local = 0;
    for (int i = beg; i < end; i++) local += g_cnt[i];

    // warp-inclusive scan
    int v = local;
    #pragma unroll
    for (int off = 1; off < 32; off <<= 1) {
        int n = __shfl_up_sync(0xFFFFFFFFu, v, off);
        if (lane >= off) v += n;
    }
    if (lane == 31) wsum[wid] = v;
    __syncthreads();
    if (wid == 0) {
        int wv = wsum[lane];
        #pragma unroll
        for (int off = 1; off < 32; off <<= 1) {
            int n = __shfl_up_sync(0xFFFFFFFFu, wv, off);
            if (lane >= off) wv += n;
        }
        wsum[lane] = wv;   // inclusive warp sums
    }
    __syncthreads();

    int excl = v - local + (wid > 0 ? wsum[wid - 1] : 0);
    if (t == T - 1) g_rowptr[N_NODES] = excl + local;   // == N_EDGES

    int acc = excl;
    for (int i = beg; i < end; i++) {
        g_rowptr[i] = acc;
        int c = g_cnt[i];
        acc += c;
        g_dinv[i] = rsqrtf(1.0f + (float)c);   // self-loop included
    }
}

__global__ void k_fill(const int* __restrict__ src,
                       const int* __restrict__ dst) {
    int e = blockIdx.x * blockDim.x + threadIdx.x;
    if (e >= N_EDGES) return;
    int d = dst[e];
    int pos = g_rowptr[d] + atomicAdd(&g_cur[d], 1);
    g_csr[pos] = src[e];
}

// ---------------- GEMM: g_xw[N,96] = X[N,96] @ W[96,96] ----------------
// 64 rows / block, 256 threads. X transposed into smem as row-pair float2
// (Xp[k][pair] = {X[2*pair][k], X[2*pair+1][k]}); accumulation in packed
// f32x2 (FFMA2): thread (ty,tx) computes row-pairs ty*4..+3, cols tx*3..+2.
__global__ void __launch_bounds__(256)
k_gemm(const float* __restrict__ Xext, const float* __restrict__ W, int use_h) {
    __shared__ float  Ws[D * D];                 // 36864 B
    __shared__ float2 Xp[D * (GR / 2)];          // 96*32 float2 = 24576 B
    const float* __restrict__ X = use_h ? (const float*)g_h : Xext;

    int t = threadIdx.x;
    int rowBase = blockIdx.x * GR;

    for (int i = t; i < D * D; i += 256) Ws[i] = W[i];

    // load X rows (float4) and transpose-pack into Xp
    float* xpf = reinterpret_cast<float*>(Xp);
    for (int i = t; i < GR * (D / 4); i += 256) {
        int r  = i / (D / 4);
        int c4 = i % (D / 4);
        int row = rowBase + r;
        float4 v = (row < N_NODES)
            ? reinterpret_cast<const float4*>(X + (size_t)row * D)[c4]
            : make_float4(0.f, 0.f, 0.f, 0.f);
        int pair = r >> 1, half = r & 1;
        int k0 = c4 * 4;
        xpf[(k0 + 0) * GR + pair * 2 + half] = v.x;
        xpf[(k0 + 1) * GR + pair * 2 + half] = v.y;
        xpf[(k0 + 2) * GR + pair * 2 + half] = v.z;
        xpf[(k0 + 3) * GR + pair * 2 + half] = v.w;
    }
    __syncthreads();

    int ty = t >> 5, tx = t & 31;
    unsigned long long acc[4][3];
    #pragma unroll
    for (int p = 0; p < 4; p++)
        #pragma unroll
        for (int c = 0; c < 3; c++) acc[p][c] = 0ull;

    const unsigned long long* xp64 =
        reinterpret_cast<const unsigned long long*>(Xp);

    #pragma unroll 2
    for (int k = 0; k < D; k++) {
        float w0 = Ws[k * D + tx * 3 + 0];
        float w1 = Ws[k * D + tx * 3 + 1];
        float w2 = Ws[k * D + tx * 3 + 2];
        unsigned long long w0p, w1p, w2p;
        PACK_F32X2(w0p, w0, w0);
        PACK_F32X2(w1p, w1, w1);
        PACK_F32X2(w2p, w2, w2);
        #pragma unroll
        for (int p = 0; p < 4; p++) {
            unsigned long long xv = xp64[k * (GR / 2) + ty * 4 + p];
            FMA_F32X2(acc[p][0], xv, w0p, acc[p][0]);
            FMA_F32X2(acc[p][1], xv, w1p, acc[p][1]);
            FMA_F32X2(acc[p][2], xv, w2p, acc[p][2]);
        }
    }

    #pragma unroll
    for (int p = 0; p < 4; p++) {
        int row0 = rowBase + (ty * 4 + p) * 2;
        #pragma unroll
        for (int c = 0; c < 3; c++) {
            float lo, hi;
            UNPACK_F32X2(lo, hi, acc[p][c]);
            if (row0 < N_NODES)     g_xw[(size_t)row0 * D + tx * 3 + c] = lo;
            if (row0 + 1 < N_NODES) g_xw[(size_t)(row0 + 1) * D + tx * 3 + c] = hi;
        }
    }
}

// ---------------- fused aggregate + bias + relu ----------------
// One warp per node; lane handles columns {lane, lane+32, lane+64}.
// Edge loop unrolled 4x so 20 independent LDGs issue per batch (MLP).
__global__ void __launch_bounds__(256)
k_agg(const float* __restrict__ b, float* __restrict__ outExt, int to_h) {
    int warp = (blockIdx.x * blockDim.x + threadIdx.x) >> 5;
    int lane = threadIdx.x & 31;
    if (warp >= N_NODES) return;
    int i = warp;

    float di = g_dinv[i];
    const float* __restrict__ xwi = g_xw + (size_t)i * D;
    float a0 = xwi[lane]      * di;
    float a1 = xwi[lane + 32] * di;
    float a2 = xwi[lane + 64] * di;

    int beg = g_rowptr[i];
    int end = g_rowptr[i + 1];
    int j = beg;

    for (; j + 4 <= end; j += 4) {
        int s0 = g_csr[j + 0];
        int s1 = g_csr[j + 1];
        int s2 = g_csr[j + 2];
        int s3 = g_csr[j + 3];
        float w0 = g_dinv[s0], w1 = g_dinv[s1], w2 = g_dinv[s2], w3 = g_dinv[s3];
        const float* __restrict__ p0 = g_xw + (size_t)s0 * D;
        const float* __restrict__ p1 = g_xw + (size_t)s1 * D;
        const float* __restrict__ p2 = g_xw + (size_t)s2 * D;
        const float* __restrict__ p3 = g_xw + (size_t)s3 * D;
        float x00 = p0[lane], x01 = p0[lane + 32], x02 = p0[lane + 64];
        float x10 = p1[lane], x11 = p1[lane + 32], x12 = p1[lane + 64];
        float x20 = p2[lane], x21 = p2[lane + 32], x22 = p2[lane + 64];
        float x30 = p3[lane], x31 = p3[lane + 32], x32 = p3[lane + 64];
        a0 += x00 * w0; a1 += x01 * w0; a2 += x02 * w0;
        a0 += x10 * w1; a1 += x11 * w1; a2 += x12 * w1;
        a0 += x20 * w2; a1 += x21 * w2; a2 += x22 * w2;
        a0 += x30 * w3; a1 += x31 * w3; a2 += x32 * w3;
    }
    for (; j < end; j++) {
        int s = g_csr[j];
        float ws = g_dinv[s];
        const float* __restrict__ xs = g_xw + (size_t)s * D;
        a0 += xs[lane]      * ws;
        a1 += xs[lane + 32] * ws;
        a2 += xs[lane + 64] * ws;
    }

    float* __restrict__ out = to_h ? g_h : outExt;
    float* op = out + (size_t)i * D;
    op[lane]      = fmaxf(a0 * di + b[lane],      0.0f);
    op[lane + 32] = fmaxf(a1 * di + b[lane + 32], 0.0f);
    op[lane + 64] = fmaxf(a2 * di + b[lane + 64], 0.0f);
}

// ---------------- launch ----------------
extern "C" void kernel_launch(void* const* d_in, const int* in_sizes, int n_in,
                              void* d_out, int out_size) {
    const float* x   = (const float*)d_in[0];
    const int*   ei  = (const int*)d_in[1];   // [2, E] int32 (JAX x64 disabled)
    const float* W1  = (const float*)d_in[2];
    const float* b1  = (const float*)d_in[3];
    const float* W2  = (const float*)d_in[4];
    const float* b2  = (const float*)d_in[5];
    float*       out = (float*)d_out;

    const int* src = ei;
    const int* dst = ei + N_EDGES;

    const int T = 256;
    int gN    = (N_NODES + T - 1) / T;
    int gE    = (N_EDGES + T - 1) / T;
    int gGemm = (N_NODES + GR - 1) / GR;
    int gAgg  = (N_NODES * 32 + T - 1) / T;   // warp per node

    // CSR build + norms (shared by both layers)
    k_zero  <<<gN, T>>>();
    k_count <<<gE, T>>>(dst);
    k_scan  <<<1, 1024>>>();
    k_fill  <<<gE, T>>>(src, dst);

    // layer 1: h = relu(agg(x @ W1) + b1)
    k_gemm <<<gGemm, T>>>(x, W1, 0);
    k_agg  <<<gAgg, T>>>(b1, out, 1);

    // layer 2: out = relu(agg(h @ W2) + b2)
    k_gemm <<<gGemm, T>>>(nullptr, W2, 1);
    k_agg  <<<gAgg, T>>>(b2, out, 0);
}